// round 7
// baseline (speedup 1.0000x reference)
#include <cuda_runtime.h>
#include <cstdint>

#define T_STEPS 128
#define NUM_BT 2048
#define NUM_LEAF 16384
#define K_DIM 384

// ---------------- static device scratch ----------------
__device__ float gA[NUM_BT * K_DIM];    // concat A rows [2048][384]
__device__ float gT3[4096 * T_STEPS];   // tproj3 transposed [g][t]
__device__ float gT2[1024 * T_STEPS];   // tproj2 transposed [h][t]
__device__ float gT1[256 * T_STEPS];    // tproj1 transposed [n][t]

__device__ __forceinline__ float softplus_f(float x) {
    // matches jax.nn.softplus: max(x,0) + log1p(exp(-|x|))
    return fmaxf(x, 0.0f) + log1pf(expf(-fabsf(x)));
}

// pack {x, x} into one f32x2 register pair
__device__ __forceinline__ unsigned long long pk2(float x) {
    unsigned long long r;
    unsigned int u = __float_as_uint(x);
    asm("mov.b64 %0, {%1, %1};" : "=l"(r) : "r"(u));
    return r;
}

#define FMA2(d, a, b) asm("fma.rn.f32x2 %0, %1, %2, %0;" : "+l"(d) : "l"(a), "l"(b))

#define UNPK(lo, hi, v) asm("mov.b64 {%0, %1}, %2;" : "=r"(lo), "=r"(hi) : "l"(v))

// ---------------------------------------------------------------------------
// Kernel 1: build A_cat[bt][k] = concat(x[bt], t_emb[t], input_vector[bt])
// ---------------------------------------------------------------------------
__global__ void prep_kernel(const float* __restrict__ x,
                            const float* __restrict__ temb,
                            const float* __restrict__ iv) {
    int idx = blockIdx.x * blockDim.x + threadIdx.x;
    if (idx >= NUM_BT * K_DIM) return;
    int bt = idx / K_DIM;
    int k = idx - bt * K_DIM;
    float v;
    if (k < 256)       v = x[bt * 256 + k];
    else if (k < 320)  v = temb[(bt & (T_STEPS - 1)) * 64 + (k - 256)];
    else               v = iv[bt * 64 + (k - 320)];
    gA[idx] = v;
}

// ---------------------------------------------------------------------------
// Kernel 2: tprojX[j][t] = t_emb[t] . tWX[j] + tbX[j]  (transposed [j][t])
// ---------------------------------------------------------------------------
__global__ void tproj_kernel(const float* __restrict__ temb,
                             const float* __restrict__ tW3, const float* __restrict__ tb3,
                             const float* __restrict__ tW2, const float* __restrict__ tb2,
                             const float* __restrict__ tW1, const float* __restrict__ tb1) {
    __shared__ float te[16 * 64];
    int tid = threadIdx.x;
    int t0 = blockIdx.y * 16;
    for (int i = tid; i < 16 * 64; i += 256) te[i] = temb[t0 * 64 + i];
    __syncthreads();

    int j = blockIdx.x * 256 + tid;
    if (j >= 4096 + 1024 + 256) return;

    const float* Wrow; float bias; float* outp;
    if (j < 4096)      { Wrow = tW3 + j * 64; bias = tb3[j]; outp = gT3 + j * T_STEPS; }
    else if (j < 5120) { int q = j - 4096; Wrow = tW2 + q * 64; bias = tb2[q]; outp = gT2 + q * T_STEPS; }
    else               { int q = j - 5120; Wrow = tW1 + q * 64; bias = tb1[q]; outp = gT1 + q * T_STEPS; }

    float w[64];
#pragma unroll
    for (int m = 0; m < 64; m++) w[m] = Wrow[m];
#pragma unroll
    for (int tt = 0; tt < 16; tt++) {
        float s = bias;
#pragma unroll
        for (int m = 0; m < 64; m++) s = fmaf(w[m], te[tt * 64 + m], s);
        outp[t0 + tt] = s;
    }
}

// ---------------------------------------------------------------------------
// Kernel 3: fused GEMM with packed fma.rn.f32x2 + dendritic-tree epilogue.
// Tile: 128 bt x 128 leaves, 256 threads, 8x8 microtile (bt packed in pairs).
// ---------------------------------------------------------------------------
__global__ __launch_bounds__(256) void main_kernel(
        const float* __restrict__ Wa, const float* __restrict__ Wt,
        const float* __restrict__ Wi, const float* __restrict__ ba,
        const float* __restrict__ w3, const float* __restrict__ w2,
        const float* __restrict__ w1, float* __restrict__ out) {

    __shared__ __align__(16) float As[8][132];                 // [k][bt] transposed
    __shared__ __align__(16) unsigned long long Bs2[8][130];   // [k][leaf] duplicated {b,b}
    __shared__ float epi[128][33];   // level-3 activations per (bt, g_local)
    __shared__ float epi2[128][9];   // level-2 activations per (bt, h_local)

    const int tid = threadIdx.x;
    const int tx = tid & 15;         // leaf cols tx*8 .. +7
    const int ty = tid >> 4;         // bt rows  ty*8 .. +7
    const int bt0 = blockIdx.y * 128;
    const int leaf0 = blockIdx.x * 128;

    unsigned long long acc[4][8];    // [bt row-pair][col], f32x2 {row 2i, row 2i+1}
#pragma unroll
    for (int i = 0; i < 4; i++)
#pragma unroll
        for (int j = 0; j < 8; j++) acc[i][j] = 0ULL;

    for (int k0 = 0; k0 < K_DIM; k0 += 8) {
        __syncthreads();
        {
            const int row = tid >> 1;           // 0..127
            const int kk4 = (tid & 1) * 4;      // 0 or 4
            // A tile (transposed store)
            float4 va = *reinterpret_cast<const float4*>(&gA[(bt0 + row) * K_DIM + k0 + kk4]);
            As[kk4 + 0][row] = va.x;
            As[kk4 + 1][row] = va.y;
            As[kk4 + 2][row] = va.z;
            As[kk4 + 3][row] = va.w;
            // B tile (duplicated f32x2 store); 8-chunks never straddle region bounds
            const float* p;
            if (k0 < 256)      p = Wa + (leaf0 + row) * 256 + k0 + kk4;
            else if (k0 < 320) p = Wt + (leaf0 + row) * 64 + (k0 - 256) + kk4;
            else               p = Wi + (leaf0 + row) * 64 + (k0 - 320) + kk4;
            float4 vb = *reinterpret_cast<const float4*>(p);
            Bs2[kk4 + 0][row] = pk2(vb.x);
            Bs2[kk4 + 1][row] = pk2(vb.y);
            Bs2[kk4 + 2][row] = pk2(vb.z);
            Bs2[kk4 + 3][row] = pk2(vb.w);
        }
        __syncthreads();

#pragma unroll
        for (int kk = 0; kk < 8; kk++) {
            // 4 f32x2 of A: adjacent bt rows are adjacent floats -> pre-packed
            ulonglong2 a01 = *reinterpret_cast<const ulonglong2*>(&As[kk][ty * 8]);
            ulonglong2 a23 = *reinterpret_cast<const ulonglong2*>(&As[kk][ty * 8 + 4]);
            unsigned long long av[4] = {a01.x, a01.y, a23.x, a23.y};
            // 8 duplicated B values
            ulonglong2 b01 = *reinterpret_cast<const ulonglong2*>(&Bs2[kk][tx * 8]);
            ulonglong2 b23 = *reinterpret_cast<const ulonglong2*>(&Bs2[kk][tx * 8 + 2]);
            ulonglong2 b45 = *reinterpret_cast<const ulonglong2*>(&Bs2[kk][tx * 8 + 4]);
            ulonglong2 b67 = *reinterpret_cast<const ulonglong2*>(&Bs2[kk][tx * 8 + 6]);
            unsigned long long bv[8] = {b01.x, b01.y, b23.x, b23.y,
                                        b45.x, b45.y, b67.x, b67.y};
#pragma unroll
            for (int i = 0; i < 4; i++)
#pragma unroll
                for (int j = 0; j < 8; j++)
                    FMA2(acc[i][j], av[i], bv[j]);
        }
    }

    // ------------------- epilogue: dendritic tree -------------------
    float ba_l[8], w3_l[8];
#pragma unroll
    for (int j = 0; j < 8; j++) {
        ba_l[j] = ba[leaf0 + tx * 8 + j];
        w3_l[j] = w3[leaf0 + tx * 8 + j];
    }

#pragma unroll
    for (int i = 0; i < 4; i++) {
        const int r0 = ty * 8 + 2 * i;       // bt row (lo lane); r0+1 = hi lane
#pragma unroll
        for (int g = 0; g < 2; g++) {
            float sg0 = 0.0f, sg1 = 0.0f;
#pragma unroll
            for (int j = 0; j < 4; j++) {
                const int col = g * 4 + j;
                unsigned int ulo, uhi;
                UNPK(ulo, uhi, acc[i][col]);
                float p0 = __uint_as_float(ulo) + ba_l[col];
                float p1 = __uint_as_float(uhi) + ba_l[col];
                sg0 = fmaf(w3_l[col], softplus_f(p0), sg0);
                sg1 = fmaf(w3_l[col], softplus_f(p1), sg1);
            }
            const int gg = (leaf0 >> 2) + tx * 2 + g;   // global g
            float p30 = sg0 + gT3[gg * T_STEPS + r0];
            float p31 = sg1 + gT3[gg * T_STEPS + r0 + 1];
            epi[r0][tx * 2 + g]     = softplus_f(p30);
            epi[r0 + 1][tx * 2 + g] = softplus_f(p31);
        }
    }
    __syncthreads();

    // level 2: 128 bt x 8 h
#pragma unroll
    for (int rep = 0; rep < 4; rep++) {
        int idx = tid + rep * 256;
        int btl = idx >> 3, hl = idx & 7;
        int ggb = blockIdx.x * 32 + hl * 4;
        float s = 0.0f;
#pragma unroll
        for (int b = 0; b < 4; b++)
            s = fmaf(w2[ggb + b], epi[btl][hl * 4 + b], s);
        float p2 = s + gT2[(blockIdx.x * 8 + hl) * T_STEPS + btl];
        epi2[btl][hl] = softplus_f(p2);
    }
    __syncthreads();

    // level 1: 128 bt x 2 n -> output
    {
        int btl = tid >> 1, nl = tid & 1;
        int n = blockIdx.x * 2 + nl;
        float s = 0.0f;
#pragma unroll
        for (int a = 0; a < 4; a++)
            s = fmaf(w1[n * 4 + a], epi2[btl][nl * 4 + a], s);
        float p1 = s + gT1[n * T_STEPS + btl];
        out[(bt0 + btl) * 256 + n] = softplus_f(p1);
    }
}

// ---------------------------------------------------------------------------
extern "C" void kernel_launch(void* const* d_in, const int* in_sizes, int n_in,
                              void* d_out, int out_size) {
    const float* x    = (const float*)d_in[0];
    const float* temb = (const float*)d_in[1];
    const float* iv   = (const float*)d_in[2];
    const float* Wa   = (const float*)d_in[3];
    const float* ba   = (const float*)d_in[4];
    const float* Wt   = (const float*)d_in[5];
    const float* Wi   = (const float*)d_in[6];
    const float* w3   = (const float*)d_in[7];
    const float* tW3  = (const float*)d_in[8];
    const float* tb3  = (const float*)d_in[9];
    const float* w2   = (const float*)d_in[10];
    const float* tW2  = (const float*)d_in[11];
    const float* tb2  = (const float*)d_in[12];
    const float* w1   = (const float*)d_in[13];
    const float* tW1  = (const float*)d_in[14];
    const float* tb1  = (const float*)d_in[15];
    float* out = (float*)d_out;

    prep_kernel<<<(NUM_BT * K_DIM + 255) / 256, 256>>>(x, temb, iv);
    tproj_kernel<<<dim3(21, 8), 256>>>(temb, tW3, tb3, tW2, tb2, tW1, tb1);
    dim3 grid(NUM_LEAF / 128, NUM_BT / 128);
    main_kernel<<<grid, 256>>>(Wa, Wt, Wi, ba, w3, w2, w1, out);
}

// round 10
// speedup vs baseline: 10.6521x; 10.6521x over previous
#include <cuda_runtime.h>
#include <cuda_bf16.h>
#include <cstdint>

#define T_STEPS 128
#define NUM_BT 2048
#define NUM_LEAF 16384
#define K_DIM 384

// ---------------- static device scratch ----------------
__device__ __align__(16) uint16_t gAb[NUM_BT * K_DIM];    // bf16 concat A [2048][384]
__device__ __align__(16) uint16_t gWb[NUM_LEAF * K_DIM];  // bf16 concat W [16384][384]
__device__ float gT3[4096 * T_STEPS];   // tproj3 transposed [g][t]
__device__ float gT2[1024 * T_STEPS];   // tproj2 transposed [h][t]
__device__ float gT1[256 * T_STEPS];    // tproj1 transposed [n][t]

__device__ __forceinline__ float softplus_fast(float x) {
    float e = __expf(-fabsf(x));
    return fmaxf(x, 0.0f) + __logf(1.0f + e);
}

__device__ __forceinline__ uint32_t pack_bf16(float a, float b) {
    __nv_bfloat162 h = __floats2bfloat162_rn(a, b);
    return *reinterpret_cast<uint32_t*>(&h);
}

__device__ __forceinline__ uint32_t smem_u32(const void* p) {
    uint32_t a;
    asm("{ .reg .u64 t; cvta.to.shared.u64 t, %1; cvt.u32.u64 %0, t; }" : "=r"(a) : "l"(p));
    return a;
}

#define LDSM4(r, addr)                                                               \
    asm volatile("ldmatrix.sync.aligned.m8n8.x4.shared.b16 {%0,%1,%2,%3}, [%4];"     \
                 : "=r"((r)[0]), "=r"((r)[1]), "=r"((r)[2]), "=r"((r)[3])            \
                 : "r"(addr))

#define MMA16816(d, a, b0, b1)                                                       \
    asm volatile("mma.sync.aligned.m16n8k16.row.col.f32.bf16.bf16.f32 "              \
                 "{%0,%1,%2,%3}, {%4,%5,%6,%7}, {%8,%9}, {%0,%1,%2,%3};"             \
                 : "+f"((d)[0]), "+f"((d)[1]), "+f"((d)[2]), "+f"((d)[3])            \
                 : "r"((a)[0]), "r"((a)[1]), "r"((a)[2]), "r"((a)[3]),               \
                   "r"(b0), "r"(b1))

// ---------------------------------------------------------------------------
// Conversion kernels: fp32 inputs -> bf16 concat matrices
// ---------------------------------------------------------------------------
__global__ void convA_kernel(const float* __restrict__ x,
                             const float* __restrict__ temb,
                             const float* __restrict__ iv) {
    int idx = blockIdx.x * 256 + threadIdx.x;
    if (idx >= NUM_BT * (K_DIM / 2)) return;
    int bt = idx / (K_DIM / 2);
    int kp = (idx - bt * (K_DIM / 2)) * 2;
    int t = bt & (T_STEPS - 1);
    float a, b;
    if (kp < 256)      { a = x[bt * 256 + kp];         b = x[bt * 256 + kp + 1]; }
    else if (kp < 320) { a = temb[t * 64 + kp - 256];  b = temb[t * 64 + kp - 255]; }
    else               { a = iv[bt * 64 + kp - 320];   b = iv[bt * 64 + kp - 319]; }
    *reinterpret_cast<uint32_t*>(gAb + bt * K_DIM + kp) = pack_bf16(a, b);
}

__global__ void convW_kernel(const float* __restrict__ Wa,
                             const float* __restrict__ Wt,
                             const float* __restrict__ Wi) {
    int idx = blockIdx.x * 256 + threadIdx.x;
    if (idx >= NUM_LEAF * (K_DIM / 2)) return;
    int leaf = idx / (K_DIM / 2);
    int kp = (idx - leaf * (K_DIM / 2)) * 2;
    float a, b;
    if (kp < 256)      { a = Wa[leaf * 256 + kp];        b = Wa[leaf * 256 + kp + 1]; }
    else if (kp < 320) { a = Wt[leaf * 64 + kp - 256];   b = Wt[leaf * 64 + kp - 255]; }
    else               { a = Wi[leaf * 64 + kp - 320];   b = Wi[leaf * 64 + kp - 319]; }
    *reinterpret_cast<uint32_t*>(gWb + leaf * K_DIM + kp) = pack_bf16(a, b);
}

// ---------------------------------------------------------------------------
// tproj kernel (transposed output [j][t])
// ---------------------------------------------------------------------------
__global__ void tproj_kernel(const float* __restrict__ temb,
                             const float* __restrict__ tW3, const float* __restrict__ tb3,
                             const float* __restrict__ tW2, const float* __restrict__ tb2,
                             const float* __restrict__ tW1, const float* __restrict__ tb1) {
    __shared__ float te[16 * 64];
    int tid = threadIdx.x;
    int t0 = blockIdx.y * 16;
    for (int i = tid; i < 16 * 64; i += 256) te[i] = temb[t0 * 64 + i];
    __syncthreads();

    int j = blockIdx.x * 256 + tid;
    if (j >= 4096 + 1024 + 256) return;

    const float* Wrow; float bias; float* outp;
    if (j < 4096)      { Wrow = tW3 + j * 64; bias = tb3[j]; outp = gT3 + j * T_STEPS; }
    else if (j < 5120) { int q = j - 4096; Wrow = tW2 + q * 64; bias = tb2[q]; outp = gT2 + q * T_STEPS; }
    else               { int q = j - 5120; Wrow = tW1 + q * 64; bias = tb1[q]; outp = gT1 + q * T_STEPS; }

    float w[64];
#pragma unroll
    for (int m = 0; m < 64; m++) w[m] = Wrow[m];
#pragma unroll
    for (int tt = 0; tt < 16; tt++) {
        float s = bias;
#pragma unroll
        for (int m = 0; m < 64; m++) s = fmaf(w[m], te[tt * 64 + m], s);
        outp[t0 + tt] = s;
    }
}

// ---------------------------------------------------------------------------
// Main kernel: bf16 mma.sync GEMM (CTA 128 bt x 128 leaf) + tree epilogue.
// 8 warps: warp_m = wid&3 (m-tile 32), warp_n = wid>>2 (n-tile 64).
// K in 12 chunks of 32. Smem rows padded to 80B (conflict-free ldmatrix).
// ---------------------------------------------------------------------------
#define ROWB 80

__global__ __launch_bounds__(256, 2) void main_kernel(
        const float* __restrict__ ba, const float* __restrict__ w3,
        const float* __restrict__ w2, const float* __restrict__ w1,
        float* __restrict__ out) {

    __shared__ __align__(16) uint8_t As[128 * ROWB];
    __shared__ __align__(16) uint8_t Bs[128 * ROWB];

    const int tid = threadIdx.x;
    const int lane = tid & 31;
    const int wid = tid >> 5;
    const int warp_m = wid & 3, warp_n = wid >> 2;
    const int m0 = warp_m * 32, n0 = warp_n * 64;
    const int bt0 = blockIdx.y * 128;
    const int leaf0 = blockIdx.x * 128;

    const uint32_t sA = smem_u32(As);
    const uint32_t sB = smem_u32(Bs);

    // ldmatrix per-thread base offsets
    const uint32_t aRowOff =
        (uint32_t)(m0 + (lane & 7) + 8 * ((lane >> 3) & 1)) * ROWB + 16 * (lane >> 4);
    const uint32_t bRowOff =
        (uint32_t)(n0 + (lane & 7) + 8 * (lane >> 4)) * ROWB + 16 * ((lane >> 3) & 1);

    float d[2][8][4];
#pragma unroll
    for (int i = 0; i < 2; i++)
#pragma unroll
        for (int j = 0; j < 8; j++)
#pragma unroll
            for (int e = 0; e < 4; e++) d[i][j][e] = 0.0f;

    const int rowL = tid >> 2;        // 0..63  (fill helper)
    const int segL = tid & 3;         // 0..3

    for (int c = 0; c < 12; c++) {
        const int k0 = c * 32;
        __syncthreads();
        // fill A and B tiles: 128 rows x 64B each, 80B smem stride
#pragma unroll
        for (int rep = 0; rep < 2; rep++) {
            int row = rowL + rep * 64;
            uint4 va = *reinterpret_cast<const uint4*>(gAb + (bt0 + row) * K_DIM + k0 + segL * 8);
            *reinterpret_cast<uint4*>(As + row * ROWB + segL * 16) = va;
            uint4 vb = *reinterpret_cast<const uint4*>(gWb + (leaf0 + row) * K_DIM + k0 + segL * 8);
            *reinterpret_cast<uint4*>(Bs + row * ROWB + segL * 16) = vb;
        }
        __syncthreads();

#pragma unroll
        for (int s = 0; s < 2; s++) {
            uint32_t a[2][4];
#pragma unroll
            for (int mi = 0; mi < 2; mi++)
                LDSM4(a[mi], sA + aRowOff + mi * (16 * ROWB) + 32 * s);
#pragma unroll
            for (int p = 0; p < 4; p++) {
                uint32_t b[4];
                LDSM4(b, sB + bRowOff + p * (16 * ROWB) + 32 * s);
#pragma unroll
                for (int mi = 0; mi < 2; mi++) {
                    MMA16816(d[mi][2 * p],     a[mi], b[0], b[1]);
                    MMA16816(d[mi][2 * p + 1], a[mi], b[2], b[3]);
                }
            }
        }
    }

    // ------------------- epilogue: dendritic tree -------------------
    const int q = lane & 3;
    const int rg = lane >> 2;
    const int bq = q >> 1;
    const int gbase = (leaf0 + n0) >> 2;
    const int hbase = (leaf0 + n0) >> 4;
    const int n_out = (leaf0 + n0) >> 6;

    float w3l[8][2], bal[8][2], w2l[8], w1l[4];
#pragma unroll
    for (int nj = 0; nj < 8; nj++) {
        int leaf = leaf0 + n0 + 8 * nj + 2 * q;
        w3l[nj][0] = __ldg(&w3[leaf]);
        w3l[nj][1] = __ldg(&w3[leaf + 1]);
        bal[nj][0] = __ldg(&ba[leaf]);
        bal[nj][1] = __ldg(&ba[leaf + 1]);
        w2l[nj] = __ldg(&w2[gbase + 2 * nj + bq]);
    }
#pragma unroll
    for (int h = 0; h < 4; h++) w1l[h] = __ldg(&w1[hbase + h]);

#pragma unroll
    for (int mi = 0; mi < 2; mi++) {
#pragma unroll
        for (int half = 0; half < 2; half++) {
            const int r = m0 + 16 * mi + 8 * half + rg;   // bt row in tile == t
            float na = 0.0f, ph = 0.0f;
#pragma unroll
            for (int nj = 0; nj < 8; nj++) {
                float e0 = d[mi][nj][2 * half];
                float e1 = d[mi][nj][2 * half + 1];
                float s = w3l[nj][0] * softplus_fast(e0 + bal[nj][0])
                        + w3l[nj][1] * softplus_fast(e1 + bal[nj][1]);
                s += __shfl_xor_sync(0xFFFFFFFFu, s, 1);
                float a2 = softplus_fast(s + gT3[(gbase + 2 * nj + bq) * T_STEPS + r]);
                float p2 = w2l[nj] * a2;
                if ((nj & 1) == 0) {
                    ph = p2;
                } else {
                    ph += p2;
                    ph += __shfl_xor_sync(0xFFFFFFFFu, ph, 2);
                    float a1 = softplus_fast(ph + gT2[(hbase + (nj >> 1)) * T_STEPS + r]);
                    na = fmaf(w1l[nj >> 1], a1, na);
                }
            }
            if (q == 0) {
                out[(bt0 + r) * 256 + n_out] =
                    softplus_fast(na + gT1[n_out * T_STEPS + r]);
            }
        }
    }
}

// ---------------------------------------------------------------------------
extern "C" void kernel_launch(void* const* d_in, const int* in_sizes, int n_in,
                              void* d_out, int out_size) {
    const float* x    = (const float*)d_in[0];
    const float* temb = (const float*)d_in[1];
    const float* iv   = (const float*)d_in[2];
    const float* Wa   = (const float*)d_in[3];
    const float* ba   = (const float*)d_in[4];
    const float* Wt   = (const float*)d_in[5];
    const float* Wi   = (const float*)d_in[6];
    const float* w3   = (const float*)d_in[7];
    const float* tW3  = (const float*)d_in[8];
    const float* tb3  = (const float*)d_in[9];
    const float* w2   = (const float*)d_in[10];
    const float* tW2  = (const float*)d_in[11];
    const float* tb2  = (const float*)d_in[12];
    const float* w1   = (const float*)d_in[13];
    const float* tW1  = (const float*)d_in[14];
    const float* tb1  = (const float*)d_in[15];
    float* out = (float*)d_out;

    convA_kernel<<<(NUM_BT * (K_DIM / 2) + 255) / 256, 256>>>(x, temb, iv);
    convW_kernel<<<(NUM_LEAF * (K_DIM / 2) + 255) / 256, 256>>>(Wa, Wt, Wi);
    tproj_kernel<<<dim3(21, 8), 256>>>(temb, tW3, tb3, tW2, tb2, tW1, tb1);
    dim3 grid(NUM_LEAF / 128, NUM_BT / 128);
    main_kernel<<<grid, 256>>>(ba, w3, w2, w1, out);
}